// round 16
// baseline (speedup 1.0000x reference)
#include <cuda_runtime.h>
#include <cstdint>

#define B_      16
#define N_      131072
#define NP_     2048
#define BPB     8                     // blocks per batch = cluster size
#define THREADS 512
#define NWARP   (THREADS / 32)        // 16
#define CHUNK   (N_ / BPB)            // 16384 points per CTA
#define PAIRS   (CHUNK / THREADS / 2) // 16 float2-pairs per thread
#define CELLS   (CHUNK / 64)          // 256 cells of 64 slots
#define NBUCK   256
// dynamic smem: xyz SoA (3*16384*4 = 196608B) + u16 origIdx (32768B) = 229376B
#define SMEM_BYTES (3 * CHUNK * 4 + CHUNK * 2)

// per-cell bboxes in global scratch (written+read by owning CTA only)
__device__ float4 g_lo[B_ * BPB * CELLS];
__device__ float4 g_hi[B_ * BPB * CELLS];

// ---------- packed f32x2 helpers (exactly-rounded per lane == scalar fp32) ----------
__device__ __forceinline__ unsigned long long pk2(float lo, float hi) {
    unsigned long long r;
    asm("mov.b64 %0, {%1, %2};" : "=l"(r) : "f"(lo), "f"(hi));
    return r;
}
__device__ __forceinline__ void up2(unsigned long long v, float& lo, float& hi) {
    asm("mov.b64 {%0, %1}, %2;" : "=f"(lo), "=f"(hi) : "l"(v));
}
__device__ __forceinline__ unsigned long long f2add(unsigned long long a, unsigned long long b) {
    unsigned long long c;
    asm("add.rn.f32x2 %0, %1, %2;" : "=l"(c) : "l"(a), "l"(b));
    return c;
}
__device__ __forceinline__ unsigned long long f2mul(unsigned long long a, unsigned long long b) {
    unsigned long long c;
    asm("mul.rn.f32x2 %0, %1, %2;" : "=l"(c) : "l"(a), "l"(b));
    return c;
}

// ---------- DSMEM helpers ----------
__device__ __forceinline__ unsigned smem_u32(const void* p) {
    return (unsigned)__cvta_generic_to_shared(p);
}
__device__ __forceinline__ unsigned mapa_rank(unsigned laddr, unsigned rk) {
    unsigned r;
    asm("mapa.shared::cluster.u32 %0, %1, %2;" : "=r"(r) : "r"(laddr), "r"(rk));
    return r;
}
__device__ __forceinline__ void stc_u64(unsigned a, unsigned long long v) {
    asm volatile("st.shared::cluster.u64 [%0], %1;" :: "r"(a), "l"(v) : "memory");
}
__device__ __forceinline__ void stc_f32(unsigned a, float v) {
    asm volatile("st.shared::cluster.f32 [%0], %1;" :: "r"(a), "f"(v) : "memory");
}

// Gaussian octile / quartile bucket key (any thresholds are correctness-neutral)
__device__ __forceinline__ int lvl8(float v) {
    return (v > -1.1503f) + (v > -0.6745f) + (v > -0.3186f) + (v > 0.0f) +
           (v > 0.3186f) + (v > 0.6745f) + (v > 1.1503f);
}
__device__ __forceinline__ int lvl4(float v) {
    return (v > -0.6745f) + (v > 0.0f) + (v > 0.6745f);
}

extern __shared__ float smem[];  // sx | sy | sz | u16 idx

__global__ void __launch_bounds__(THREADS, 1) __cluster_dims__(BPB, 1, 1)
fps_kernel(const float* __restrict__ xyz,
           const int*  __restrict__ finit,   // int32
           float*      __restrict__ out)     // float32
{
    __shared__ int cnt[NBUCK];
    __shared__ unsigned long long sKey[2][BPB];
    __shared__ float sCx[2][BPB], sCy[2][BPB], sCz[2][BPB];
    __shared__ unsigned long long sKeyBuf[NWARP];
    __shared__ int sSlotBuf[NWARP];

    const int t    = threadIdx.x;
    const int blk  = blockIdx.x;
    const int b    = blk / BPB;
    const int rank = blk % BPB;
    const int lane = t & 31;
    const int warp = t >> 5;
    const unsigned rankBase = (unsigned)(rank * CHUNK);

    float* sx = smem;
    float* sy = smem + CHUNK;
    float* sz = smem + 2 * CHUNK;
    unsigned short* sIdx = (unsigned short*)(smem + 3 * CHUNK);

    const float* xb  = xyz + (size_t)b * N_ * 3;
    const float* src = xb + (size_t)rank * CHUNK * 3;

    // ================= one-time: counting-sort chunk into spatial buckets ======
    for (int i = t; i < NBUCK; i += THREADS) cnt[i] = 0;
    __syncthreads();
    for (int p = t; p < CHUNK; p += THREADS) {
        float x = src[3 * p], y = src[3 * p + 1], z = src[3 * p + 2];
        atomicAdd(&cnt[lvl8(x) * 32 + lvl8(y) * 4 + lvl4(z)], 1);
    }
    __syncthreads();
    if (t == 0) {
        int run = 0;
        for (int i = 0; i < NBUCK; i++) { int c = cnt[i]; cnt[i] = run; run += c; }
    }
    __syncthreads();
    for (int p = t; p < CHUNK; p += THREADS) {
        float x = src[3 * p], y = src[3 * p + 1], z = src[3 * p + 2];
        int k = lvl8(x) * 32 + lvl8(y) * 4 + lvl4(z);
        int slot = atomicAdd(&cnt[k], 1);
        sx[slot] = x; sy[slot] = y; sz[slot] = z;
        sIdx[slot] = (unsigned short)p;
    }
    __syncthreads();

    // ---- per-cell exact bboxes (64 slots/cell) -> global scratch ----
    const int cbase = blk * CELLS;
    for (int c = warp; c < CELLS; c += NWARP) {
        int p0 = c * 64 + 2 * lane;
        float lx = fminf(sx[p0], sx[p0 + 1]), hx = fmaxf(sx[p0], sx[p0 + 1]);
        float ly = fminf(sy[p0], sy[p0 + 1]), hy = fmaxf(sy[p0], sy[p0 + 1]);
        float lz = fminf(sz[p0], sz[p0 + 1]), hz = fmaxf(sz[p0], sz[p0 + 1]);
#pragma unroll
        for (int off = 16; off; off >>= 1) {
            lx = fminf(lx, __shfl_xor_sync(0xFFFFFFFFu, lx, off));
            hx = fmaxf(hx, __shfl_xor_sync(0xFFFFFFFFu, hx, off));
            ly = fminf(ly, __shfl_xor_sync(0xFFFFFFFFu, ly, off));
            hy = fmaxf(hy, __shfl_xor_sync(0xFFFFFFFFu, hy, off));
            lz = fminf(lz, __shfl_xor_sync(0xFFFFFFFFu, lz, off));
            hz = fmaxf(hz, __shfl_xor_sync(0xFFFFFFFFu, hz, off));
        }
        if (lane == 0) {
            g_lo[cbase + c] = make_float4(lx, ly, lz, 0.0f);
            g_hi[cbase + c] = make_float4(hx, hy, hz, 0.0f);
        }
    }
    __syncthreads();   // orders smem + global writes within CTA

    // initial centroid (batch-global original index)
    unsigned cur = (unsigned)finit[b];
    if (cur >= (unsigned)N_) cur %= (unsigned)N_;
    float cxs = xb[(size_t)cur * 3 + 0];
    float cys = xb[(size_t)cur * 3 + 1];
    float czs = xb[(size_t)cur * 3 + 2];

    float dist[2 * PAIRS];
#pragma unroll
    for (int i = 0; i < 2 * PAIRS; i++) dist[i] = 1e10f;

    for (int s = 0;; ++s) {
        if (rank == 0 && t == 0) out[(size_t)b * NP_ + s] = (float)cur;
        if (s == NP_ - 1) break;

        const unsigned long long ncx = pk2(-cxs, -cxs);
        const unsigned long long ncy = pk2(-cys, -cys);
        const unsigned long long ncz = pk2(-czs, -czs);

        float bv = -1.0f;
#pragma unroll
        for (int j = 0; j < PAIRS; j++) {
            const int c = j * NWARP + warp;           // this warp's cell for j
            const int l = j * (2 * THREADS) + 2 * t;  // slot pair (8B aligned)

            // rigorous lower bound of squared distance to cell bbox (round-down)
            float4 lo = __ldg(&g_lo[cbase + c]);
            float4 hi = __ldg(&g_hi[cbase + c]);
            float ax = fmaxf(fmaxf(__fsub_rd(lo.x, cxs), __fsub_rd(cxs, hi.x)), 0.0f);
            float ay = fmaxf(fmaxf(__fsub_rd(lo.y, cys), __fsub_rd(cys, hi.y)), 0.0f);
            float az = fmaxf(fmaxf(__fsub_rd(lo.z, czs), __fsub_rd(czs, hi.z)), 0.0f);
            float lb = __fadd_rd(__fadd_rd(__fmul_rd(ax, ax), __fmul_rd(ay, ay)),
                                 __fmul_rd(az, az));

            float pm = fmaxf(dist[2 * j], dist[2 * j + 1]);
            bool need = !(__fmul_rd(lb, 0.98f) > pm);   // safe skip margin
            if (__any_sync(0xFFFFFFFFu, need)) {
                float2 xv = *reinterpret_cast<const float2*>(sx + l);
                float2 yv = *reinterpret_cast<const float2*>(sy + l);
                float2 zv = *reinterpret_cast<const float2*>(sz + l);
                unsigned long long dx = f2add(pk2(xv.x, xv.y), ncx);
                unsigned long long dy = f2add(pk2(yv.x, yv.y), ncy);
                unsigned long long dz = f2add(pk2(zv.x, zv.y), ncz);
                // XLA order: (dx^2 + dy^2) + dz^2, no FMA contraction
                unsigned long long ss =
                    f2add(f2add(f2mul(dx, dx), f2mul(dy, dy)), f2mul(dz, dz));
                float s0, s1;
                up2(ss, s0, s1);
                float d0 = fminf(dist[2 * j], s0);
                float d1 = fminf(dist[2 * j + 1], s1);
                dist[2 * j] = d0;
                dist[2 * j + 1] = d1;
                pm = fmaxf(d0, d1);
            }
            bv = fmaxf(bv, pm);
        }

        // ---- rescan: among dist==bv pick smallest ORIGINAL index (exact ties) ----
        unsigned bi = 0xFFFFFFFFu;
        int bslot = 0;
#pragma unroll
        for (int j = 0; j < PAIRS; j++) {
            const int l = j * (2 * THREADS) + 2 * t;
            float d0 = dist[2 * j], d1 = dist[2 * j + 1];
            if (d0 == bv || d1 == bv) {
                unsigned pr = *reinterpret_cast<const unsigned*>(sIdx + l);
                if (d0 == bv) {
                    unsigned oi = rankBase + (pr & 0xFFFFu);
                    if (oi < bi) { bi = oi; bslot = l; }
                }
                if (d1 == bv) {
                    unsigned oi = rankBase + (pr >> 16);
                    if (oi < bi) { bi = oi; bslot = l + 1; }
                }
            }
        }

        // ---- warp reduce on key=(value, ~origIdx), carrying slot ----
        unsigned long long key =
            ((unsigned long long)__float_as_uint(bv) << 32) | (~bi);
#pragma unroll
        for (int off = 16; off; off >>= 1) {
            unsigned long long ok = __shfl_down_sync(0xFFFFFFFFu, key, off);
            int os = __shfl_down_sync(0xFFFFFFFFu, bslot, off);
            if (ok > key) { key = ok; bslot = os; }
        }
        if (lane == 0) { sKeyBuf[warp] = key; sSlotBuf[warp] = bslot; }
        __syncthreads();

        // ---- warp 0: bfly over 16 warp keys; lanes 0..7 publish to peers ----
        if (warp == 0) {
            unsigned long long k = (lane < NWARP) ? sKeyBuf[lane] : 0ull;
            int sl = (lane < NWARP) ? sSlotBuf[lane] : 0;
#pragma unroll
            for (int off = 16; off; off >>= 1) {
                unsigned long long ok = __shfl_xor_sync(0xFFFFFFFFu, k, off);
                int os = __shfl_xor_sync(0xFFFFFFFFu, sl, off);
                if (ok > k) { k = ok; sl = os; }
            }
            if (lane < BPB) {
                float x = sx[sl], y = sy[sl], z = sz[sl];
                const int pp = s & 1;
                stc_u64(mapa_rank(smem_u32(&sKey[pp][rank]), (unsigned)lane), k);
                stc_f32(mapa_rank(smem_u32(&sCx[pp][rank]), (unsigned)lane), x);
                stc_f32(mapa_rank(smem_u32(&sCy[pp][rank]), (unsigned)lane), y);
                stc_f32(mapa_rank(smem_u32(&sCz[pp][rank]), (unsigned)lane), z);
            }
        }

        asm volatile("barrier.cluster.arrive.aligned;" ::: "memory");
        asm volatile("barrier.cluster.wait.aligned;" ::: "memory");

        const int pp = s & 1;
        unsigned long long kb = 0;
        int br = 0;
#pragma unroll
        for (int r = 0; r < BPB; r++) {
            unsigned long long k = sKey[pp][r];
            if (k > kb) { kb = k; br = r; }
        }
        cur = ~(unsigned)kb;     // batch-global ORIGINAL index
        cxs = sCx[pp][br];
        cys = sCy[pp][br];
        czs = sCz[pp][br];
    }
}

extern "C" void kernel_launch(void* const* d_in, const int* in_sizes, int n_in,
                              void* d_out, int out_size)
{
    // d_in[0]=xyz f32 [16,131072,3], d_in[1]=farthest_init i32 [16], d_in[2]=npoints
    int xi = 0;
    for (int i = 1; i < n_in; i++)
        if (in_sizes[i] > in_sizes[xi]) xi = i;
    int fi = -1;
    for (int i = 0; i < n_in; i++)
        if (i != xi && in_sizes[i] > 1 && (fi < 0 || in_sizes[i] < in_sizes[fi])) fi = i;
    if (fi < 0) fi = (xi == 0 && n_in > 1) ? 1 : 0;

    cudaFuncSetAttribute(fps_kernel, cudaFuncAttributeMaxDynamicSharedMemorySize, SMEM_BYTES);
    fps_kernel<<<B_ * BPB, THREADS, SMEM_BYTES>>>(
        (const float*)d_in[xi], (const int*)d_in[fi], (float*)d_out);
}

// round 17
// speedup vs baseline: 1.7724x; 1.7724x over previous
#include <cuda_runtime.h>
#include <cstdint>

#define B_      16
#define N_      131072
#define NP_     2048
#define BPB     8                     // blocks per batch = cluster size
#define THREADS 512
#define NWARP   (THREADS / 32)        // 16
#define CHUNK   (N_ / BPB)            // 16384 points per CTA
#define NPAIR   (CHUNK / 2)           // 8192 pairs per CTA
#define PAIRS_T (NPAIR / THREADS)     // 16 pairs per thread
// dynamic smem: xy float4[NPAIR] = 128KB, z float2[NPAIR] = 64KB  -> 192KB
#define SMEM_BYTES (NPAIR * 16 + NPAIR * 8)

// ---------- packed f32x2 helpers (exactly-rounded per lane == scalar fp32) ----------
__device__ __forceinline__ unsigned long long pk2(float lo, float hi) {
    unsigned long long r;
    asm("mov.b64 %0, {%1, %2};" : "=l"(r) : "f"(lo), "f"(hi));
    return r;
}
__device__ __forceinline__ void up2(unsigned long long v, float& lo, float& hi) {
    asm("mov.b64 {%0, %1}, %2;" : "=f"(lo), "=f"(hi) : "l"(v));
}
__device__ __forceinline__ unsigned long long f2add(unsigned long long a, unsigned long long b) {
    unsigned long long c;
    asm("add.rn.f32x2 %0, %1, %2;" : "=l"(c) : "l"(a), "l"(b));
    return c;
}
__device__ __forceinline__ unsigned long long f2mul(unsigned long long a, unsigned long long b) {
    unsigned long long c;
    asm("mul.rn.f32x2 %0, %1, %2;" : "=l"(c) : "l"(a), "l"(b));
    return c;
}

// ---------- DSMEM helpers ----------
__device__ __forceinline__ unsigned smem_u32(const void* p) {
    return (unsigned)__cvta_generic_to_shared(p);
}
__device__ __forceinline__ unsigned mapa_rank(unsigned laddr, unsigned rk) {
    unsigned r;
    asm("mapa.shared::cluster.u32 %0, %1, %2;" : "=r"(r) : "r"(laddr), "r"(rk));
    return r;
}
__device__ __forceinline__ void stc_u64(unsigned a, unsigned long long v) {
    asm volatile("st.shared::cluster.u64 [%0], %1;" :: "r"(a), "l"(v) : "memory");
}
__device__ __forceinline__ void stc_f32(unsigned a, float v) {
    asm volatile("st.shared::cluster.f32 [%0], %1;" :: "r"(a), "f"(v) : "memory");
}

extern __shared__ float4 smem4[];  // xy[NPAIR] | z (as float2[NPAIR])

__global__ void __launch_bounds__(THREADS, 1) __cluster_dims__(BPB, 1, 1)
fps_kernel(const float* __restrict__ xyz,
           const int*  __restrict__ finit,   // int32 (verified)
           float*      __restrict__ out)     // float32 (checker reads f32)
{
    // cluster-combine slots, double-buffered by step parity
    __shared__ unsigned long long sKey[2][BPB];
    __shared__ float sCx[2][BPB], sCy[2][BPB], sCz[2][BPB];
    __shared__ unsigned long long sKeyBuf[NWARP];

    const int t    = threadIdx.x;
    const int blk  = blockIdx.x;
    const int b    = blk / BPB;
    const int rank = blk % BPB;
    const int lane = t & 31;
    const int warp = t >> 5;
    const unsigned rankBase = (unsigned)(rank * CHUNK);

    float4* sxy = smem4;                                  // [NPAIR] x0,x1,y0,y1
    float2* szp = (float2*)(smem4 + NPAIR);               // [NPAIR] z0,z1

    const float* xb  = xyz + (size_t)b * N_ * 3;
    const float* src = xb + (size_t)rank * CHUNK * 3;

    // ---- one-time: load chunk into pair-packed SMEM (2 loads/pair in mainloop) ----
    for (int P = t; P < NPAIR; P += THREADS) {
        const float* s6 = src + 6 * P;       // points 2P, 2P+1
        sxy[P] = make_float4(s6[0], s6[3], s6[1], s6[4]);  // x0,x1,y0,y1
        szp[P] = make_float2(s6[2], s6[5]);                // z0,z1
    }
    __syncthreads();

    // initial centroid (batch-global index)
    unsigned cur = (unsigned)finit[b];
    if (cur >= (unsigned)N_) cur %= (unsigned)N_;
    float cxs = xb[(size_t)cur * 3 + 0];
    float cys = xb[(size_t)cur * 3 + 1];
    float czs = xb[(size_t)cur * 3 + 2];

    // register-resident min distances (init 1e10 per reference; re-init per launch)
    float dist[2 * PAIRS_T];
#pragma unroll
    for (int i = 0; i < 2 * PAIRS_T; i++) dist[i] = 1e10f;

    for (int s = 0;; ++s) {
        if (rank == 0 && t == 0) out[(size_t)b * NP_ + s] = (float)cur;
        if (s == NP_ - 1) break;

        const unsigned long long ncx = pk2(-cxs, -cxs);
        const unsigned long long ncy = pk2(-cys, -cys);
        const unsigned long long ncz = pk2(-czs, -czs);

        // ---- hot loop: 2 LDS + 8 packed ops + 2 min + 2 max per pair ----
        float bv0 = -1.0f, bv1 = -1.0f;
#pragma unroll
        for (int j = 0; j < PAIRS_T; j++) {
            const int P = j * THREADS + t;
            float4 xy = sxy[P];
            float2 zz = szp[P];
            unsigned long long dx = f2add(pk2(xy.x, xy.y), ncx);
            unsigned long long dy = f2add(pk2(xy.z, xy.w), ncy);
            unsigned long long dz = f2add(pk2(zz.x, zz.y), ncz);
            // XLA order: (dx^2 + dy^2) + dz^2, no FMA contraction
            unsigned long long ss =
                f2add(f2add(f2mul(dx, dx), f2mul(dy, dy)), f2mul(dz, dz));
            float s0, s1;
            up2(ss, s0, s1);
            float m0 = fminf(dist[2 * j], s0);
            dist[2 * j] = m0;
            bv0 = fmaxf(bv0, m0);
            float m1 = fminf(dist[2 * j + 1], s1);
            dist[2 * j + 1] = m1;
            bv1 = fmaxf(bv1, m1);
        }
        float bv = fmaxf(bv0, bv1);

        // ---- rescan: first (smallest chunk-local) index holding bv (exact) ----
        unsigned bi = 0;
#pragma unroll
        for (int j = PAIRS_T - 1; j >= 0; --j) {
            const unsigned l = 2u * (unsigned)(j * THREADS + t);
            if (dist[2 * j + 1] == bv) bi = l + 1;
            if (dist[2 * j]     == bv) bi = l;
        }

        // ---- warp reduce on key=(value, ~globalIdx): max value, tie -> min idx ----
        unsigned long long key =
            ((unsigned long long)__float_as_uint(bv) << 32) | (~(rankBase + bi));
#pragma unroll
        for (int off = 16; off; off >>= 1) {
            unsigned long long ok = __shfl_down_sync(0xFFFFFFFFu, key, off);
            if (ok > key) key = ok;
        }
        if (lane == 0) sKeyBuf[warp] = key;

        // ---- barrier split: only warp 0 waits for the 16 keys ----
        if (warp != 0) {
            asm volatile("bar.arrive 1, 512;" ::: "memory");
        } else {
            asm volatile("bar.sync 1, 512;" ::: "memory");
            unsigned long long k = (lane < NWARP) ? sKeyBuf[lane] : 0ull;
#pragma unroll
            for (int off = 16; off; off >>= 1) {
                unsigned long long ok = __shfl_xor_sync(0xFFFFFFFFu, k, off);
                if (ok > k) k = ok;
            }
            if (lane < BPB) {
                unsigned li = (~(unsigned)k) - rankBase;   // CTA-local winner idx
                unsigned P  = li >> 1;
                float4 xy = sxy[P];
                float2 zz = szp[P];
                float x = (li & 1) ? xy.y : xy.x;
                float y = (li & 1) ? xy.w : xy.z;
                float z = (li & 1) ? zz.y : zz.x;
                const int pp = s & 1;
                stc_u64(mapa_rank(smem_u32(&sKey[pp][rank]), (unsigned)lane), k);
                stc_f32(mapa_rank(smem_u32(&sCx[pp][rank]), (unsigned)lane), x);
                stc_f32(mapa_rank(smem_u32(&sCy[pp][rank]), (unsigned)lane), y);
                stc_f32(mapa_rank(smem_u32(&sCz[pp][rank]), (unsigned)lane), z);
            }
        }

        // cluster barrier: warp0's arrive (after publish) releases its stores
        asm volatile("barrier.cluster.arrive.aligned;" ::: "memory");
        asm volatile("barrier.cluster.wait.aligned;" ::: "memory");

        // every thread reduces the 8 slots identically (broadcast LDS)
        const int pp = s & 1;
        unsigned long long kb = 0;
        int br = 0;
#pragma unroll
        for (int r = 0; r < BPB; r++) {
            unsigned long long k = sKey[pp][r];
            if (k > kb) { kb = k; br = r; }
        }
        cur = ~(unsigned)kb;                 // batch-global index
        cxs = sCx[pp][br];
        cys = sCy[pp][br];
        czs = sCz[pp][br];
    }
}

extern "C" void kernel_launch(void* const* d_in, const int* in_sizes, int n_in,
                              void* d_out, int out_size)
{
    // d_in[0]=xyz f32 [16,131072,3], d_in[1]=farthest_init i32 [16], d_in[2]=npoints
    int xi = 0;
    for (int i = 1; i < n_in; i++)
        if (in_sizes[i] > in_sizes[xi]) xi = i;
    int fi = -1;
    for (int i = 0; i < n_in; i++)
        if (i != xi && in_sizes[i] > 1 && (fi < 0 || in_sizes[i] < in_sizes[fi])) fi = i;
    if (fi < 0) fi = (xi == 0 && n_in > 1) ? 1 : 0;

    cudaFuncSetAttribute(fps_kernel, cudaFuncAttributeMaxDynamicSharedMemorySize, SMEM_BYTES);
    fps_kernel<<<B_ * BPB, THREADS, SMEM_BYTES>>>(
        (const float*)d_in[xi], (const int*)d_in[fi], (float*)d_out);
}